// round 3
// baseline (speedup 1.0000x reference)
#include <cuda_runtime.h>

#define N_NODES 100000
#define N_EDGES 1000000
#define HID 64
#define SCAN_BLK 1024                       // items per scan block
#define N_SBLK ((N_NODES + SCAN_BLK - 1) / SCAN_BLK)   // 98

// ---- scratch (static device globals; no runtime allocation) ----
__device__ __align__(16) float g_xw_user[N_NODES * HID];
__device__ __align__(16) float g_xw_movie[N_NODES * HID];
__device__ __align__(16) float g_acc_user[N_NODES * HID];
__device__ __align__(16) float g_acc_movie[N_NODES * HID];
__device__ float  g_deg[N_NODES];
__device__ float  g_dinv[N_NODES];
__device__ int    g_count[N_NODES];
__device__ int    g_off[N_NODES + 1];
__device__ int    g_cursor[N_NODES];
__device__ int    g_bsum[N_SBLK];
__device__ int    g_bsumx[N_SBLK];
__device__ __align__(8) float2 g_edge[N_EDGES];   // {row_as_int_bits, norm}

// ---------------------------------------------------------------------------
// K1: xw = x @ W for both node types; init deg=1 (self-loop), count=0.
// ---------------------------------------------------------------------------
__global__ __launch_bounds__(256) void k1_xw(
    const float* __restrict__ ux, const float* __restrict__ mx,
    const float* __restrict__ Wu, const float* __restrict__ Wm) {
    int gid = blockIdx.x * blockDim.x + threadIdx.x;
    if (gid >= N_NODES * 16) return;
    int n = gid >> 4;
    int c = gid & 15;

    float4 su = make_float4(0.f, 0.f, 0.f, 0.f);
#pragma unroll
    for (int k = 0; k < 3; k++) {
        float xv = ux[n * 3 + k];
        float4 w = *(const float4*)(Wu + k * HID + c * 4);
        su.x += xv * w.x; su.y += xv * w.y; su.z += xv * w.z; su.w += xv * w.w;
    }
    *(float4*)(g_xw_user + (size_t)n * HID + c * 4) = su;

    float4 sm = make_float4(0.f, 0.f, 0.f, 0.f);
#pragma unroll
    for (int k = 0; k < 18; k++) {
        float xv = mx[n * 18 + k];
        float4 w = *(const float4*)(Wm + k * HID + c * 4);
        sm.x += xv * w.x; sm.y += xv * w.y; sm.z += xv * w.z; sm.w += xv * w.w;
    }
    *(float4*)(g_xw_movie + (size_t)n * HID + c * 4) = sm;

    if (c == 0) {
        g_deg[n] = 1.0f;   // self-loop weight
        g_count[n] = 0;
    }
}

// ---------------------------------------------------------------------------
// K2: weighted degree and in-degree count per destination node.
// ---------------------------------------------------------------------------
__global__ __launch_bounds__(256) void k2_deg(
    const int* __restrict__ ei, const float* __restrict__ ew) {
    int e = blockIdx.x * blockDim.x + threadIdx.x;
    if (e >= N_EDGES) return;
    int col = ei[N_EDGES + e];
    atomicAdd(&g_deg[col], ew[e]);
    atomicAdd(&g_count[col], 1);
}

// ---------------------------------------------------------------------------
// K3: dinv = rsqrt(deg)   (deg >= 1 always, so no zero guard needed)
// ---------------------------------------------------------------------------
__global__ __launch_bounds__(256) void k3_dinv() {
    int n = blockIdx.x * blockDim.x + threadIdx.x;
    if (n >= N_NODES) return;
    g_dinv[n] = rsqrtf(g_deg[n]);
}

// ---------------------------------------------------------------------------
// S1: per-block exclusive scan of counts (1024 items / block of 256 threads)
// ---------------------------------------------------------------------------
__global__ __launch_bounds__(256) void s1_scan() {
    __shared__ int ts[256];
    int t = threadIdx.x;
    int base = blockIdx.x * SCAN_BLK + t * 4;
    int v[4];
    int s = 0;
#pragma unroll
    for (int i = 0; i < 4; i++) {
        v[i] = (base + i < N_NODES) ? g_count[base + i] : 0;
        s += v[i];
    }
    ts[t] = s;
    __syncthreads();
    // inclusive Hillis-Steele over the 256 thread sums
    for (int off = 1; off < 256; off <<= 1) {
        int add = (t >= off) ? ts[t - off] : 0;
        __syncthreads();
        ts[t] += add;
        __syncthreads();
    }
    int run = ts[t] - s;  // exclusive thread prefix
#pragma unroll
    for (int i = 0; i < 4; i++) {
        if (base + i < N_NODES) g_off[base + i] = run;
        run += v[i];
    }
    if (t == 255) g_bsum[blockIdx.x] = ts[255];
}

// ---------------------------------------------------------------------------
// S2: single-block exclusive scan of the 98 block sums.
// ---------------------------------------------------------------------------
__global__ __launch_bounds__(128) void s2_scan() {
    __shared__ int bs[128];
    int t = threadIdx.x;
    int orig = (t < N_SBLK) ? g_bsum[t] : 0;
    bs[t] = orig;
    __syncthreads();
    for (int off = 1; off < 128; off <<= 1) {
        int add = (t >= off) ? bs[t - off] : 0;
        __syncthreads();
        bs[t] += add;
        __syncthreads();
    }
    if (t < N_SBLK) g_bsumx[t] = bs[t] - orig;
    if (t == 0) g_off[N_NODES] = N_EDGES;
}

// ---------------------------------------------------------------------------
// S3: finalize offsets, init cursors.
// ---------------------------------------------------------------------------
__global__ __launch_bounds__(256) void s3_finish() {
    int n = blockIdx.x * blockDim.x + threadIdx.x;
    if (n >= N_NODES) return;
    int o = g_off[n] + g_bsumx[n / SCAN_BLK];
    g_off[n] = o;
    g_cursor[n] = o;
}

// ---------------------------------------------------------------------------
// F: fill CSR slots with (row, norm).
// ---------------------------------------------------------------------------
__global__ __launch_bounds__(256) void f_fill(
    const int* __restrict__ ei, const float* __restrict__ ew) {
    int e = blockIdx.x * blockDim.x + threadIdx.x;
    if (e >= N_EDGES) return;
    int row = ei[e];
    int col = ei[N_EDGES + e];
    float norm = g_dinv[row] * ew[e] * g_dinv[col];
    int pos = atomicAdd(&g_cursor[col], 1);
    g_edge[pos] = make_float2(__int_as_float(row), norm);
}

// ---------------------------------------------------------------------------
// G: gather. Warp per destination node. Lane c<16 owns user float4 c,
//    lane c>=16 owns movie float4 c-16. Self-loop fused.
// ---------------------------------------------------------------------------
__global__ __launch_bounds__(256) void g_gather() {
    unsigned gid = blockIdx.x * blockDim.x + threadIdx.x;
    unsigned n = gid >> 5;
    int c = gid & 31;
    if (n >= N_NODES) return;

    const float* src = (c < 16) ? g_xw_user : g_xw_movie;
    float* dst = (c < 16) ? g_acc_user : g_acc_movie;
    int c4 = (c & 15) * 4;

    float din = g_dinv[n];
    float s = din * din;                           // self-loop norm
    float4 v = *(const float4*)(src + (size_t)n * HID + c4);
    float4 a = make_float4(s * v.x, s * v.y, s * v.z, s * v.w);

    int j = g_off[n];
    int end = g_off[n + 1];
    for (; j < end; j++) {
        float2 ed = g_edge[j];                     // broadcast across warp
        int row = __float_as_int(ed.x);
        float nm = ed.y;
        float4 u = *(const float4*)(src + (size_t)row * HID + c4);
        a.x += nm * u.x; a.y += nm * u.y; a.z += nm * u.z; a.w += nm * u.w;
    }
    *(float4*)(dst + (size_t)n * HID + c4) = a;
}

// ---------------------------------------------------------------------------
// K5: fused MLP. h[n] = [acc_user[n]+b_user, acc_movie[n]+b_movie] (128)
//     out[n] = relu(h @ W1 + b1) . W2 + b2
//     256 threads, tile 128 nodes x 128 cols, 8x8 register blocking.
// ---------------------------------------------------------------------------
#define HS_STRIDE 36
#define W1S_STRIDE 132

__global__ __launch_bounds__(256) void k5_mlp(
    const float* __restrict__ bu, const float* __restrict__ bm,
    const float* __restrict__ W1, const float* __restrict__ b1,
    const float* __restrict__ W2, const float* __restrict__ b2,
    float* __restrict__ out) {
    __shared__ float hs[128 * HS_STRIDE];
    __shared__ float w1s[32 * W1S_STRIDE];
    __shared__ float redbuf[128 * 16];

    int tid = threadIdx.x;
    int nbase = blockIdx.x * 128;
    int cg = tid & 15;
    int ng = tid >> 4;

    float acc[8][8];
#pragma unroll
    for (int i = 0; i < 8; i++)
#pragma unroll
        for (int j = 0; j < 8; j++) acc[i][j] = 0.f;

    for (int kc = 0; kc < 4; kc++) {
        int k0 = kc * 32;
        __syncthreads();

#pragma unroll
        for (int it = 0; it < 4; it++) {
            int idx = it * 256 + tid;
            int r = idx >> 5;
            int c4 = idx & 31;
            float4 w = *(const float4*)(W1 + (k0 + r) * 128 + c4 * 4);
            *(float4*)(w1s + r * W1S_STRIDE + c4 * 4) = w;
        }

#pragma unroll
        for (int it = 0; it < 4; it++) {
            int idx = it * 256 + tid;
            int nl = idx >> 3;
            int k4 = idx & 7;
            int n = nbase + nl;
            int k = k0 + k4 * 4;
            float4 v;
            if (n < N_NODES) {
                if (k < HID) {
                    v = *(const float4*)(g_acc_user + (size_t)n * HID + k);
                    float4 b = *(const float4*)(bu + k);
                    v.x += b.x; v.y += b.y; v.z += b.z; v.w += b.w;
                } else {
                    v = *(const float4*)(g_acc_movie + (size_t)n * HID + (k - HID));
                    float4 b = *(const float4*)(bm + (k - HID));
                    v.x += b.x; v.y += b.y; v.z += b.z; v.w += b.w;
                }
            } else {
                v = make_float4(0.f, 0.f, 0.f, 0.f);
            }
            *(float4*)(hs + nl * HS_STRIDE + k4 * 4) = v;
        }
        __syncthreads();

#pragma unroll
        for (int kk = 0; kk < 32; kk++) {
            float4 wa = *(const float4*)(w1s + kk * W1S_STRIDE + cg * 8);
            float4 wb = *(const float4*)(w1s + kk * W1S_STRIDE + cg * 8 + 4);
            float hv[8];
#pragma unroll
            for (int i = 0; i < 8; i++)
                hv[i] = hs[(ng * 8 + i) * HS_STRIDE + kk];
#pragma unroll
            for (int i = 0; i < 8; i++) {
                acc[i][0] += hv[i] * wa.x;
                acc[i][1] += hv[i] * wa.y;
                acc[i][2] += hv[i] * wa.z;
                acc[i][3] += hv[i] * wa.w;
                acc[i][4] += hv[i] * wb.x;
                acc[i][5] += hv[i] * wb.y;
                acc[i][6] += hv[i] * wb.z;
                acc[i][7] += hv[i] * wb.w;
            }
        }
    }

    float b1v[8], w2v[8];
#pragma unroll
    for (int j = 0; j < 8; j++) {
        b1v[j] = b1[cg * 8 + j];
        w2v[j] = W2[cg * 8 + j];
    }
    __syncthreads();
#pragma unroll
    for (int i = 0; i < 8; i++) {
        float p = 0.f;
#pragma unroll
        for (int j = 0; j < 8; j++) {
            float t = acc[i][j] + b1v[j];
            t = t > 0.f ? t : 0.f;
            p += t * w2v[j];
        }
        redbuf[(ng * 8 + i) * 16 + cg] = p;
    }
    __syncthreads();
    if (tid < 128) {
        int n = nbase + tid;
        if (n < N_NODES) {
            float s = 0.f;
#pragma unroll
            for (int g = 0; g < 16; g++) s += redbuf[tid * 16 + g];
            out[n] = s + b2[0];
        }
    }
}

// ---------------------------------------------------------------------------
extern "C" void kernel_launch(void* const* d_in, const int* in_sizes, int n_in,
                              void* d_out, int out_size) {
    const float* user_x   = (const float*)d_in[0];
    const float* movie_x  = (const float*)d_in[1];
    const int*   edge_idx = (const int*)d_in[2];    // int32 (JAX x64 disabled)
    const float* edge_w   = (const float*)d_in[3];
    const float* W_user   = (const float*)d_in[4];
    const float* b_user   = (const float*)d_in[5];
    const float* W_movie  = (const float*)d_in[6];
    const float* b_movie  = (const float*)d_in[7];
    const float* W1       = (const float*)d_in[8];
    const float* b1       = (const float*)d_in[9];
    const float* W2       = (const float*)d_in[10];
    const float* b2       = (const float*)d_in[11];
    float* out = (float*)d_out;

    k1_xw  <<<(N_NODES * 16 + 255) / 256, 256>>>(user_x, movie_x, W_user, W_movie);
    k2_deg <<<(N_EDGES + 255) / 256, 256>>>(edge_idx, edge_w);
    k3_dinv<<<(N_NODES + 255) / 256, 256>>>();
    s1_scan<<<N_SBLK, 256>>>();
    s2_scan<<<1, 128>>>();
    s3_finish<<<(N_NODES + 255) / 256, 256>>>();
    f_fill <<<(N_EDGES + 255) / 256, 256>>>(edge_idx, edge_w);
    g_gather<<<(N_NODES * 32 + 255) / 256, 256>>>();
    k5_mlp <<<(N_NODES + 127) / 128, 256>>>(b_user, b_movie, W1, b1, W2, b2, out);
}

// round 5
// speedup vs baseline: 1.4533x; 1.4533x over previous
#include <cuda_runtime.h>
#include <cuda_bf16.h>
#include <cstdint>

#define N_NODES 100000
#define N_EDGES 1000000
#define HID 64
#define N_TILES 782                          // ceil(100000/128)
#define SCAN_BLK 1024
#define N_SBLK ((N_NODES + SCAN_BLK - 1) / SCAN_BLK)   // 98

// ---- scratch (static device globals; no runtime allocation) ----
__device__ __align__(16) float g_xw_user[N_NODES * HID];
__device__ __align__(16) float g_xw_movie[N_NODES * HID];
__device__ float  g_deg[N_NODES];
__device__ float  g_dinv[N_NODES];
__device__ int    g_count[N_NODES];
__device__ int    g_off[N_NODES + 1];
__device__ int    g_cursor[N_NODES];
__device__ int    g_bsum[N_SBLK];
__device__ int    g_bsumx[N_SBLK];
__device__ __align__(8) float2 g_edge[N_EDGES];   // {row_as_int_bits, norm}

// bf16 split images, plain row-major:
//   g_hA/g_lA: [tile][m=128][k=128]  (h hi / lo)
//   g_hB/g_lB: [n=128][k=128]        (W1^T hi / lo)
__device__ uint4 g_hA[N_TILES * 2048];
__device__ uint4 g_lA[N_TILES * 2048];
__device__ uint4 g_hB[2048];
__device__ uint4 g_lB[2048];

__device__ __forceinline__ unsigned pk2(__nv_bfloat16 a, __nv_bfloat16 b) {
    __nv_bfloat162 t; t.x = a; t.y = b;
    return *(unsigned*)&t;
}

// ---------------------------------------------------------------------------
// K1: xw = x @ W for both node types; init deg=1, count=0.
//     First 16384 threads also convert W1 -> [n][k] bf16 hi/lo image.
// ---------------------------------------------------------------------------
__global__ __launch_bounds__(256) void k1_xw(
    const float* __restrict__ ux, const float* __restrict__ mx,
    const float* __restrict__ Wu, const float* __restrict__ Wm,
    const float* __restrict__ W1) {
    int gid = blockIdx.x * blockDim.x + threadIdx.x;
    if (gid >= N_NODES * 16) return;

    if (gid < 16384) {           // k = gid>>7, n = gid&127
        int k = gid >> 7;
        int n = gid & 127;
        float w = W1[k * 128 + n];
        __nv_bfloat16 h = __float2bfloat16(w);
        __nv_bfloat16 l = __float2bfloat16(w - __bfloat162float(h));
        ((__nv_bfloat16*)g_hB)[n * 128 + k] = h;
        ((__nv_bfloat16*)g_lB)[n * 128 + k] = l;
    }

    int n = gid >> 4;
    int c = gid & 15;

    float4 su = make_float4(0.f, 0.f, 0.f, 0.f);
#pragma unroll
    for (int k = 0; k < 3; k++) {
        float xv = ux[n * 3 + k];
        float4 w = *(const float4*)(Wu + k * HID + c * 4);
        su.x += xv * w.x; su.y += xv * w.y; su.z += xv * w.z; su.w += xv * w.w;
    }
    *(float4*)(g_xw_user + (size_t)n * HID + c * 4) = su;

    float4 sm = make_float4(0.f, 0.f, 0.f, 0.f);
#pragma unroll
    for (int k = 0; k < 18; k++) {
        float xv = mx[n * 18 + k];
        float4 w = *(const float4*)(Wm + k * HID + c * 4);
        sm.x += xv * w.x; sm.y += xv * w.y; sm.z += xv * w.z; sm.w += xv * w.w;
    }
    *(float4*)(g_xw_movie + (size_t)n * HID + c * 4) = sm;

    if (c == 0) {
        g_deg[n] = 1.0f;
        g_count[n] = 0;
    }
}

// ---------------------------------------------------------------------------
// K2: weighted degree and in-degree count per destination node.
// ---------------------------------------------------------------------------
__global__ __launch_bounds__(256) void k2_deg(
    const int* __restrict__ ei, const float* __restrict__ ew) {
    int e = blockIdx.x * blockDim.x + threadIdx.x;
    if (e >= N_EDGES) return;
    int col = ei[N_EDGES + e];
    atomicAdd(&g_deg[col], ew[e]);
    atomicAdd(&g_count[col], 1);
}

// ---------------------------------------------------------------------------
// S1: per-block exclusive scan of counts; dinv fused.
// ---------------------------------------------------------------------------
__global__ __launch_bounds__(256) void s1_scan() {
    __shared__ int ts[256];
    int t = threadIdx.x;
    int base = blockIdx.x * SCAN_BLK + t * 4;
    int v[4];
    int s = 0;
#pragma unroll
    for (int i = 0; i < 4; i++) {
        int idx = base + i;
        if (idx < N_NODES) {
            v[i] = g_count[idx];
            g_dinv[idx] = rsqrtf(g_deg[idx]);
        } else v[i] = 0;
        s += v[i];
    }
    ts[t] = s;
    __syncthreads();
    for (int off = 1; off < 256; off <<= 1) {
        int add = (t >= off) ? ts[t - off] : 0;
        __syncthreads();
        ts[t] += add;
        __syncthreads();
    }
    int run = ts[t] - s;
#pragma unroll
    for (int i = 0; i < 4; i++) {
        if (base + i < N_NODES) g_off[base + i] = run;
        run += v[i];
    }
    if (t == 255) g_bsum[blockIdx.x] = ts[255];
}

// ---------------------------------------------------------------------------
// S2: single-block exclusive scan of the 98 block sums.
// ---------------------------------------------------------------------------
__global__ __launch_bounds__(128) void s2_scan() {
    __shared__ int bs[128];
    int t = threadIdx.x;
    int orig = (t < N_SBLK) ? g_bsum[t] : 0;
    bs[t] = orig;
    __syncthreads();
    for (int off = 1; off < 128; off <<= 1) {
        int add = (t >= off) ? bs[t - off] : 0;
        __syncthreads();
        bs[t] += add;
        __syncthreads();
    }
    if (t < N_SBLK) g_bsumx[t] = bs[t] - orig;
    if (t == 0) g_off[N_NODES] = N_EDGES;
}

// ---------------------------------------------------------------------------
// S3: finalize offsets, init cursors.
// ---------------------------------------------------------------------------
__global__ __launch_bounds__(256) void s3_finish() {
    int n = blockIdx.x * blockDim.x + threadIdx.x;
    if (n >= N_NODES) return;
    int o = g_off[n] + g_bsumx[n / SCAN_BLK];
    g_off[n] = o;
    g_cursor[n] = o;
}

// ---------------------------------------------------------------------------
// F: fill CSR slots with (row, norm).
// ---------------------------------------------------------------------------
__global__ __launch_bounds__(256) void f_fill(
    const int* __restrict__ ei, const float* __restrict__ ew) {
    int e = blockIdx.x * blockDim.x + threadIdx.x;
    if (e >= N_EDGES) return;
    int row = ei[e];
    int col = ei[N_EDGES + e];
    float norm = g_dinv[row] * ew[e] * g_dinv[col];
    int pos = atomicAdd(&g_cursor[col], 1);
    g_edge[pos] = make_float2(__int_as_float(row), norm);
}

// ---------------------------------------------------------------------------
// G: gather. Warp per destination node; fp32 accumulate; bias fused;
//    split-bf16 hi/lo written to plain row-major tile images.
// ---------------------------------------------------------------------------
__global__ __launch_bounds__(256) void g_gather(
    const float* __restrict__ bu, const float* __restrict__ bm) {
    unsigned gid = blockIdx.x * blockDim.x + threadIdx.x;
    unsigned n = gid >> 5;
    int c = gid & 31;
    if (n >= N_NODES) return;

    const float* src = (c < 16) ? g_xw_user : g_xw_movie;
    const float* bias = (c < 16) ? bu : bm;
    int c4 = (c & 15) * 4;

    float din = g_dinv[n];
    float s = din * din;
    float4 v = *(const float4*)(src + (size_t)n * HID + c4);
    float4 a = make_float4(s * v.x, s * v.y, s * v.z, s * v.w);

    int j = g_off[n];
    int end = g_off[n + 1];
    for (; j < end; j++) {
        float2 ed = g_edge[j];
        int row = __float_as_int(ed.x);
        float nm = ed.y;
        float4 u = *(const float4*)(src + (size_t)row * HID + c4);
        a.x += nm * u.x; a.y += nm * u.y; a.z += nm * u.z; a.w += nm * u.w;
    }
    float4 b = *(const float4*)(bias + c4);
    a.x += b.x; a.y += b.y; a.z += b.z; a.w += b.w;

    __nv_bfloat16 h0 = __float2bfloat16(a.x), h1 = __float2bfloat16(a.y);
    __nv_bfloat16 h2 = __float2bfloat16(a.z), h3 = __float2bfloat16(a.w);
    __nv_bfloat16 l0 = __float2bfloat16(a.x - __bfloat162float(h0));
    __nv_bfloat16 l1 = __float2bfloat16(a.y - __bfloat162float(h1));
    __nv_bfloat16 l2 = __float2bfloat16(a.z - __bfloat162float(h2));
    __nv_bfloat16 l3 = __float2bfloat16(a.w - __bfloat162float(h3));

    unsigned tile = n >> 7;
    unsigned m = n & 127;
    int k0 = (c < 16) ? c4 : (64 + c4);
    size_t off = (size_t)tile * 32768 + m * 256 + k0 * 2;   // bytes
    *(uint2*)((char*)g_hA + off) = make_uint2(pk2(h0, h1), pk2(h2, h3));
    *(uint2*)((char*)g_lA + off) = make_uint2(pk2(l0, l1), pk2(l2, l3));
}

// ---------------------------------------------------------------------------
// K5: split-bf16 GEMM via mma.sync.m16n8k16 + fused relu/W2 epilogue.
//     Block = 256 thr (8 warps); warp w owns rows 16w..16w+15, all 128 cols.
//     smem images padded to 272B/row -> conflict-free fragment loads.
// ---------------------------------------------------------------------------
#define PITCH    272
#define SM_AHI   0
#define SM_ALO   (128 * PITCH)
#define SM_BHI   (2 * 128 * PITCH)
#define SM_BLO   (3 * 128 * PITCH)
#define SM_B1    (4 * 128 * PITCH)
#define SM_W2    (SM_B1 + 512)
#define SM_TOT   (SM_W2 + 512)

__global__ __launch_bounds__(256, 1)
void k5_mma(const float* __restrict__ b1, const float* __restrict__ W2,
            const float* __restrict__ b2, float* __restrict__ out) {
    extern __shared__ char smem[];
    int tid = threadIdx.x;
    int w = tid >> 5;
    int lane = tid & 31;
    int tile = blockIdx.x;

    // stage b1 / W2
    if (tid < 128) {
        ((float*)(smem + SM_B1))[tid] = b1[tid];
        ((float*)(smem + SM_W2))[tid] = W2[tid];
    }
    // stage A hi/lo (tile) and B hi/lo (shared weights) with row pad
    {
        const uint4* gah = g_hA + (size_t)tile * 2048;
        const uint4* gal = g_lA + (size_t)tile * 2048;
#pragma unroll
        for (int i = tid; i < 2048; i += 256) {
            int r = i >> 4, c16 = (i & 15) * 16;
            *(uint4*)(smem + SM_AHI + r * PITCH + c16) = gah[i];
            *(uint4*)(smem + SM_ALO + r * PITCH + c16) = gal[i];
            *(uint4*)(smem + SM_BHI + r * PITCH + c16) = g_hB[i];
            *(uint4*)(smem + SM_BLO + r * PITCH + c16) = g_lB[i];
        }
    }
    __syncthreads();

    float acc[16][4];
#pragma unroll
    for (int nt = 0; nt < 16; nt++)
#pragma unroll
        for (int j = 0; j < 4; j++) acc[nt][j] = 0.f;

    int gq = lane >> 2;        // fragment group row 0..7
    int q4 = (lane & 3) * 4;   // k-byte sub-offset

    const int aoffs[3] = {SM_AHI, SM_AHI, SM_ALO};
    const int boffs[3] = {SM_BHI, SM_BLO, SM_BHI};

#pragma unroll
    for (int ch = 0; ch < 3; ch++) {
        const char* As = smem + aoffs[ch] + (w * 16 + gq) * PITCH;
        const char* Bs = smem + boffs[ch] + gq * PITCH;
#pragma unroll
        for (int ks = 0; ks < 8; ks++) {
            int kb = ks * 32 + q4;
            uint32_t a0 = *(const uint32_t*)(As + kb);
            uint32_t a1 = *(const uint32_t*)(As + 8 * PITCH + kb);
            uint32_t a2 = *(const uint32_t*)(As + kb + 16);
            uint32_t a3 = *(const uint32_t*)(As + 8 * PITCH + kb + 16);
#pragma unroll
            for (int nt = 0; nt < 16; nt++) {
                uint32_t b0 = *(const uint32_t*)(Bs + nt * 8 * PITCH + kb);
                uint32_t b1v = *(const uint32_t*)(Bs + nt * 8 * PITCH + kb + 16);
                asm volatile(
                    "mma.sync.aligned.m16n8k16.row.col.f32.bf16.bf16.f32 "
                    "{%0,%1,%2,%3}, {%4,%5,%6,%7}, {%8,%9}, {%0,%1,%2,%3};"
                    : "+f"(acc[nt][0]), "+f"(acc[nt][1]),
                      "+f"(acc[nt][2]), "+f"(acc[nt][3])
                    : "r"(a0), "r"(a1), "r"(a2), "r"(a3), "r"(b0), "r"(b1v));
            }
        }
    }

    // epilogue: relu(acc + b1) . W2, lane-local then shfl over 4-lane groups
    const float* b1s = (const float*)(smem + SM_B1);
    const float* w2s = (const float*)(smem + SM_W2);
    float p0 = 0.f, p1 = 0.f;
#pragma unroll
    for (int nt = 0; nt < 16; nt++) {
        int cn = nt * 8 + (lane & 3) * 2;
        float bb0 = b1s[cn], bb1 = b1s[cn + 1];
        float ww0 = w2s[cn], ww1 = w2s[cn + 1];
        float t;
        t = acc[nt][0] + bb0; t = t > 0.f ? t : 0.f; p0 += t * ww0;
        t = acc[nt][1] + bb1; t = t > 0.f ? t : 0.f; p0 += t * ww1;
        t = acc[nt][2] + bb0; t = t > 0.f ? t : 0.f; p1 += t * ww0;
        t = acc[nt][3] + bb1; t = t > 0.f ? t : 0.f; p1 += t * ww1;
    }
    p0 += __shfl_xor_sync(0xFFFFFFFF, p0, 1);
    p0 += __shfl_xor_sync(0xFFFFFFFF, p0, 2);
    p1 += __shfl_xor_sync(0xFFFFFFFF, p1, 1);
    p1 += __shfl_xor_sync(0xFFFFFFFF, p1, 2);

    if ((lane & 3) == 0) {
        float bias2 = b2[0];
        int r0 = tile * 128 + w * 16 + gq;
        int r1 = r0 + 8;
        if (r0 < N_NODES) out[r0] = p0 + bias2;
        if (r1 < N_NODES) out[r1] = p1 + bias2;
    }
}

// ---------------------------------------------------------------------------
extern "C" void kernel_launch(void* const* d_in, const int* in_sizes, int n_in,
                              void* d_out, int out_size) {
    const float* user_x   = (const float*)d_in[0];
    const float* movie_x  = (const float*)d_in[1];
    const int*   edge_idx = (const int*)d_in[2];    // int32 (JAX x64 disabled)
    const float* edge_w   = (const float*)d_in[3];
    const float* W_user   = (const float*)d_in[4];
    const float* b_user   = (const float*)d_in[5];
    const float* W_movie  = (const float*)d_in[6];
    const float* b_movie  = (const float*)d_in[7];
    const float* W1       = (const float*)d_in[8];
    const float* b1       = (const float*)d_in[9];
    const float* W2       = (const float*)d_in[10];
    const float* b2       = (const float*)d_in[11];
    float* out = (float*)d_out;

    static int smem_set = 0;
    if (!smem_set) {
        cudaFuncSetAttribute(k5_mma, cudaFuncAttributeMaxDynamicSharedMemorySize, SM_TOT);
        smem_set = 1;
    }

    k1_xw  <<<(N_NODES * 16 + 255) / 256, 256>>>(user_x, movie_x, W_user, W_movie, W1);
    k2_deg <<<(N_EDGES + 255) / 256, 256>>>(edge_idx, edge_w);
    s1_scan<<<N_SBLK, 256>>>();
    s2_scan<<<1, 128>>>();
    s3_finish<<<(N_NODES + 255) / 256, 256>>>();
    f_fill <<<(N_EDGES + 255) / 256, 256>>>(edge_idx, edge_w);
    g_gather<<<(N_NODES * 32 + 255) / 256, 256>>>(b_user, b_movie);
    k5_mma <<<N_TILES, 256, SM_TOT>>>(b1, W2, b2, out);
}